// round 3
// baseline (speedup 1.0000x reference)
#include <cuda_runtime.h>

// ---------------------------------------------------------------------------
// KAN-Mixer token-mixing block, fused as two feature-GEMMs.
//   rows r = (b, c)  (B*C = 49152 rows)
//   fc1:  h1[r, o] = sum_k F1[r, k] * Wc1[k, o] + b1[o],   k = p*9 + j (j<8 rbf, j=8 silu)
//   fc2:  h2[r, p] = sum_k F2[r, k] * Wc2[k, p] + b2[p],   k = h*9 + j
//   out[b, p, c] = h2[(b,c), p] + x[b, p, c]
// fp32 with packed fma.rn.f32x2 (2 MACs/lane/instr).
// ---------------------------------------------------------------------------

constexpr int Bn  = 64;
constexpr int Pn  = 196;
constexpr int Cn  = 768;
constexpr int HSn = 384;
constexpr int K1n = Pn * 9;    // 1764
constexpr int K2n = HSn * 9;   // 3456
constexpr int NP2 = 256;       // fc2 output cols padded 196 -> 256 (zeros)
constexpr int ROWSn = Bn * Cn; // 49152

// scratch (static __device__ arrays: allocation-free per harness rules)
__device__ float g_Wc1T[K1n * HSn];            // [K1][384]   fused fc1 weights
__device__ float g_Wc2T[K2n * NP2];            // [K2][256]   fused fc2 weights (padded)
__device__ float g_h1T[(size_t)HSn * ROWSn];   // [HS][B*C]   transposed intermediate

#define DINLINE __device__ __forceinline__

DINLINE unsigned long long pack2f(float x, float y) {
    unsigned long long r;
    asm("mov.b64 %0, {%1, %2};" : "=l"(r) : "f"(x), "f"(y));
    return r;
}
DINLINE void unpack2f(unsigned long long v, float &x, float &y) {
    asm("mov.b64 {%0, %1}, %2;" : "=f"(x), "=f"(y) : "l"(v));
}
DINLINE void fma2(unsigned long long &d, unsigned long long a, unsigned long long b) {
    asm("fma.rn.f32x2 %0, %1, %2, %0;" : "+l"(d) : "l"(a), "l"(b));
}

// 9 features of one scalar: 8 gaussian RBF over grid [-1,1] (NG=8) + silu.
// (x - g_i)/denom = (x+1)*3.5 - i
DINLINE void features9(float xv, float* dst, int stride) {
    float u = (xv + 1.0f) * 3.5f;
#pragma unroll
    for (int i = 0; i < 8; i++) {
        float t = u - (float)i;
        dst[i * stride] = __expf(-t * t);
    }
    dst[8 * stride] = xv / (1.0f + __expf(-xv));
}

// ---------------------------------------------------------------------------
// weight prepack: interleave spline (8) + base (1) rows, k-major, N contiguous
// ---------------------------------------------------------------------------
__global__ void prepack1_kernel(const float* __restrict__ sw, const float* __restrict__ bw) {
    int idx = blockIdx.x * blockDim.x + threadIdx.x;
    if (idx >= K1n * HSn) return;
    int o = idx % HSn, k = idx / HSn;
    int p = k / 9, j = k - p * 9;
    g_Wc1T[idx] = (j < 8) ? sw[(size_t)o * (Pn * 8) + p * 8 + j] : bw[(size_t)o * Pn + p];
}
__global__ void prepack2_kernel(const float* __restrict__ sw, const float* __restrict__ bw) {
    int idx = blockIdx.x * blockDim.x + threadIdx.x;
    if (idx >= K2n * NP2) return;
    int col = idx % NP2, k = idx / NP2;
    int h = k / 9, j = k - h * 9;
    float v = 0.0f;
    if (col < Pn) v = (j < 8) ? sw[(size_t)col * (HSn * 8) + h * 8 + j] : bw[(size_t)col * HSn + h];
    g_Wc2T[idx] = v;
}

// ---------------------------------------------------------------------------
// fc1: tile 128 rows(c) x 128 outs(o); K chunks of 4 patches = 36 features
// grid (3, 6, 64), 256 threads, micro-tile 8x8 per thread (row-pair f32x2)
// ---------------------------------------------------------------------------
__global__ void __launch_bounds__(256, 2)
fc1_kernel(const float* __restrict__ x, const float* __restrict__ b1) {
    __shared__ float Fs[36 * 128];
    __shared__ float Ws[36 * 128];
    const int tid = threadIdx.x;
    const int o0 = blockIdx.x * 128;
    const int c0 = blockIdx.y * 128;
    const int b  = blockIdx.z;
    const int rg = tid >> 4;   // 16 row-groups of 8 rows
    const int cg = tid & 15;   // 16 col-groups of 8 cols

    unsigned long long acc[4][8];
#pragma unroll
    for (int ip = 0; ip < 4; ip++)
#pragma unroll
        for (int j = 0; j < 8; j++) acc[ip][j] = 0ull;

    const float* xb = x + (size_t)b * Pn * Cn + c0;

    for (int ch = 0; ch < 49; ch++) {
        const int p0 = ch * 4;
        __syncthreads();
        // features: 4 patches x 128 rows, lane-consecutive rows (coalesced LDG, conflict-free STS)
        for (int idx = tid; idx < 512; idx += 256) {
            int row = idx & 127, pp = idx >> 7;
            float xv = xb[(size_t)(p0 + pp) * Cn + row];
            features9(xv, Fs + (pp * 9) * 128 + row, 128);
        }
        // weights: 36 x 128 floats
        {
            const float4* wsrc = reinterpret_cast<const float4*>(g_Wc1T + (size_t)(p0 * 9) * HSn + o0);
            float4* wdst = reinterpret_cast<float4*>(Ws);
            for (int idx = tid; idx < 1152; idx += 256) {
                int k = idx >> 5, cv = idx & 31;
                wdst[k * 32 + cv] = wsrc[k * 96 + cv];
            }
        }
        __syncthreads();
#pragma unroll 2
        for (int k = 0; k < 36; k++) {
            const float2* fr = reinterpret_cast<const float2*>(Fs + k * 128) + rg * 4;
            unsigned long long pa[4];
#pragma unroll
            for (int ip = 0; ip < 4; ip++) { float2 t = fr[ip]; pa[ip] = pack2f(t.x, t.y); }
            const float4* wr = reinterpret_cast<const float4*>(Ws + k * 128) + cg * 2;
            float4 w0 = wr[0], w1 = wr[1];
            unsigned long long pb[8] = {
                pack2f(w0.x, w0.x), pack2f(w0.y, w0.y), pack2f(w0.z, w0.z), pack2f(w0.w, w0.w),
                pack2f(w1.x, w1.x), pack2f(w1.y, w1.y), pack2f(w1.z, w1.z), pack2f(w1.w, w1.w)};
#pragma unroll
            for (int ip = 0; ip < 4; ip++)
#pragma unroll
                for (int j = 0; j < 8; j++) fma2(acc[ip][j], pa[ip], pb[j]);
        }
    }
    // epilogue: transposed store h1T[o][b*768 + c] (row dim contiguous for pass 2)
    const size_t rowbase = (size_t)b * Cn + c0 + rg * 8;
#pragma unroll
    for (int j = 0; j < 8; j++) {
        int o = o0 + cg * 8 + j;
        float bias = b1[o];
        float v[8];
#pragma unroll
        for (int ip = 0; ip < 4; ip++) unpack2f(acc[ip][j], v[2 * ip], v[2 * ip + 1]);
        float* dst = g_h1T + (size_t)o * ROWSn + rowbase;
        reinterpret_cast<float4*>(dst)[0] =
            make_float4(v[0] + bias, v[1] + bias, v[2] + bias, v[3] + bias);
        reinterpret_cast<float4*>(dst)[1] =
            make_float4(v[4] + bias, v[5] + bias, v[6] + bias, v[7] + bias);
    }
}

// ---------------------------------------------------------------------------
// fc2: tile 128 rows(c) x 128 outs(p, padded to 256); K chunks of 4 hidden = 36 feats
// grid (2, 6, 64), 256 threads, micro-tile 8x8; epilogue adds bias + skip x
// ---------------------------------------------------------------------------
__global__ void __launch_bounds__(256, 2)
fc2_kernel(const float* __restrict__ x, const float* __restrict__ b2, float* __restrict__ out) {
    __shared__ float Fs[36 * 128];
    __shared__ float Ws[36 * 128];
    const int tid = threadIdx.x;
    const int p0 = blockIdx.x * 128;
    const int c0 = blockIdx.y * 128;
    const int b  = blockIdx.z;
    const int rg = tid >> 4;   // 16 row-groups of 8 rows
    const int cg = tid & 15;   // 16 col-groups of 8 cols

    unsigned long long acc[4][8];
#pragma unroll
    for (int ip = 0; ip < 4; ip++)
#pragma unroll
        for (int j = 0; j < 8; j++) acc[ip][j] = 0ull;

    const size_t rowb = (size_t)b * Cn + c0;

    for (int ch = 0; ch < 96; ch++) {
        const int k0 = ch * 4;
        __syncthreads();
        // features from transposed h1 (fully coalesced: row contiguous)
        for (int idx = tid; idx < 512; idx += 256) {
            int row = idx & 127, kk = idx >> 7;
            float hv = g_h1T[(size_t)(k0 + kk) * ROWSn + rowb + row];
            features9(hv, Fs + (kk * 9) * 128 + row, 128);
        }
        // weights: 36 x 128 floats
        {
            const float4* wsrc = reinterpret_cast<const float4*>(g_Wc2T + (size_t)(k0 * 9) * NP2 + p0);
            float4* wdst = reinterpret_cast<float4*>(Ws);
            for (int idx = tid; idx < 1152; idx += 256) {
                int k = idx >> 5, cv = idx & 31;
                wdst[k * 32 + cv] = wsrc[k * 64 + cv];
            }
        }
        __syncthreads();
#pragma unroll 2
        for (int k = 0; k < 36; k++) {
            const float2* fr = reinterpret_cast<const float2*>(Fs + k * 128) + rg * 4;
            unsigned long long pa[4];
#pragma unroll
            for (int ip = 0; ip < 4; ip++) { float2 t = fr[ip]; pa[ip] = pack2f(t.x, t.y); }
            const float4* wr = reinterpret_cast<const float4*>(Ws + k * 128) + cg * 2;
            float4 w0 = wr[0], w1 = wr[1];
            unsigned long long pb[8] = {
                pack2f(w0.x, w0.x), pack2f(w0.y, w0.y), pack2f(w0.z, w0.z), pack2f(w0.w, w0.w),
                pack2f(w1.x, w1.x), pack2f(w1.y, w1.y), pack2f(w1.z, w1.z), pack2f(w1.w, w1.w)};
#pragma unroll
            for (int ip = 0; ip < 4; ip++)
#pragma unroll
                for (int j = 0; j < 8; j++) fma2(acc[ip][j], pa[ip], pb[j]);
        }
    }
    // epilogue: out[b, p, c] = acc + b2[p] + x[b, p, c]   (mask padded p >= 196)
#pragma unroll
    for (int j = 0; j < 8; j++) {
        int p = p0 + cg * 8 + j;
        if (p < Pn) {
            float bias = b2[p];
            float v[8];
#pragma unroll
            for (int ip = 0; ip < 4; ip++) unpack2f(acc[ip][j], v[2 * ip], v[2 * ip + 1]);
            size_t base = (size_t)b * Pn * Cn + (size_t)p * Cn + c0 + rg * 8;
            float4 x0 = reinterpret_cast<const float4*>(x + base)[0];
            float4 x1 = reinterpret_cast<const float4*>(x + base)[1];
            float4* od = reinterpret_cast<float4*>(out + base);
            od[0] = make_float4(v[0] + bias + x0.x, v[1] + bias + x0.y,
                                v[2] + bias + x0.z, v[3] + bias + x0.w);
            od[1] = make_float4(v[4] + bias + x1.x, v[5] + bias + x1.y,
                                v[6] + bias + x1.z, v[7] + bias + x1.w);
        }
    }
}

// ---------------------------------------------------------------------------
extern "C" void kernel_launch(void* const* d_in, const int* in_sizes, int n_in,
                              void* d_out, int out_size) {
    const float* x   = (const float*)d_in[0];
    const float* w1s = (const float*)d_in[1];
    const float* w1b = (const float*)d_in[2];
    const float* b1  = (const float*)d_in[3];
    const float* w2s = (const float*)d_in[4];
    const float* w2b = (const float*)d_in[5];
    const float* b2  = (const float*)d_in[6];
    float* out = (float*)d_out;

    prepack1_kernel<<<(K1n * HSn + 255) / 256, 256>>>(w1s, w1b);
    prepack2_kernel<<<(K2n * NP2 + 255) / 256, 256>>>(w2s, w2b);
    fc1_kernel<<<dim3(HSn / 128, Cn / 128, Bn), 256>>>(x, b1);
    fc2_kernel<<<dim3(NP2 / 128, Cn / 128, Bn), 256>>>(x, b2, out);
}